// round 1
// baseline (speedup 1.0000x reference)
#include <cuda_runtime.h>
#include <math.h>
#include <stdint.h>

// Problem constants (fixed by the dataset problem)
#define HDIM 2048
#define NEXP 16
#define IDIM 768
#define TWO_I 1536
#define TMAX 4096           // max tokens supported (actual T = 2048)
#define PMAX (TMAX*2)       // max dispatched (token, expert) pairs

// ---------------- device scratch (no allocations allowed) ----------------
__device__ int   g_count[NEXP];
__device__ int   g_cursor[NEXP];
__device__ int   g_segstart[NEXP + 1];
__device__ int   g_tok_e[TMAX * 2];
__device__ float g_tok_w[TMAX * 2];
__device__ int   g_pair_token[PMAX];
__device__ float g_pair_w[PMAX];
__device__ float g_h[(size_t)PMAX * IDIM];        // SwiGLU activations, 25 MB
__device__ float g_logits_fallback[TMAX * NEXP];  // used if harness out has no logits slot

// ---------------- kernel 0: reset counters ----------------
__global__ void init_kernel() {
    int i = threadIdx.x;
    if (i < NEXP) g_count[i] = 0;
}

// ---------------- kernel 1: router (logits, softmax top-2, counts) ----------------
__global__ __launch_bounds__(128) void router_kernel(
    const float* __restrict__ x, const float* __restrict__ gw,
    float* __restrict__ logits, int T)
{
    int t = blockIdx.x;
    int tid = threadIdx.x;

    float acc[NEXP];
#pragma unroll
    for (int e = 0; e < NEXP; e++) acc[e] = 0.f;

    const float* xr = x + (size_t)t * HDIM;
    for (int h = tid; h < HDIM; h += 128) {
        float xv = xr[h];
#pragma unroll
        for (int e = 0; e < NEXP; e++) acc[e] += xv * gw[e * HDIM + h];
    }

    // intra-warp reduce
#pragma unroll
    for (int e = 0; e < NEXP; e++) {
#pragma unroll
        for (int off = 16; off > 0; off >>= 1)
            acc[e] += __shfl_down_sync(0xffffffffu, acc[e], off);
    }

    __shared__ float sred[4][NEXP];
    __shared__ float slog[NEXP];
    int warp = tid >> 5, lane = tid & 31;
    if (lane == 0) {
#pragma unroll
        for (int e = 0; e < NEXP; e++) sred[warp][e] = acc[e];
    }
    __syncthreads();
    if (tid < NEXP) {
        float v = sred[0][tid] + sred[1][tid] + sred[2][tid] + sred[3][tid];
        slog[tid] = v;
        logits[t * NEXP + tid] = v;
    }
    __syncthreads();

    if (tid == 0) {
        // top-2, lowest index wins ties (matches jax.lax.top_k)
        int i0 = 0; float v0 = slog[0];
#pragma unroll
        for (int e = 1; e < NEXP; e++) { if (slog[e] > v0) { v0 = slog[e]; i0 = e; } }
        int i1 = -1; float v1 = -INFINITY;
#pragma unroll
        for (int e = 0; e < NEXP; e++) {
            if (e == i0) continue;
            if (slog[e] > v1) { v1 = slog[e]; i1 = e; }
        }
        // normalized top-2 weights: softmax Z cancels
        float e1 = expf(v1 - v0);
        float inv = 1.f / (1.f + e1);
        g_tok_e[t * 2 + 0] = i0;  g_tok_w[t * 2 + 0] = inv;        // w0 = 1/(1+e1)
        g_tok_e[t * 2 + 1] = i1;  g_tok_w[t * 2 + 1] = e1 * inv;   // w1 = e1/(1+e1)
        atomicAdd(&g_count[i0], 1);
        atomicAdd(&g_count[i1], 1);
    }
}

// ---------------- kernel 2: segment offsets ----------------
__global__ void offsets_kernel() {
    if (threadIdx.x == 0) {
        int off = 0;
#pragma unroll
        for (int e = 0; e < NEXP; e++) {
            g_segstart[e] = off;
            off += g_count[e];
            g_cursor[e] = 0;
        }
        g_segstart[NEXP] = off;
    }
}

// ---------------- kernel 3: dispatch tokens into expert segments ----------------
__global__ void dispatch_kernel(int T) {
    int t = blockIdx.x * blockDim.x + threadIdx.x;
    if (t >= T) return;
#pragma unroll
    for (int s = 0; s < 2; s++) {
        int e = g_tok_e[t * 2 + s];
        int pos = g_segstart[e] + atomicAdd(&g_cursor[e], 1);
        g_pair_token[pos] = t;
        g_pair_w[pos]     = g_tok_w[t * 2 + s];
    }
}

// ---------------- kernel 4: zero output ----------------
__global__ void zero_kernel(float* __restrict__ out, size_t n4) {
    size_t i = (size_t)blockIdx.x * blockDim.x + threadIdx.x;
    if (i < n4) ((float4*)out)[i] = make_float4(0.f, 0.f, 0.f, 0.f);
}

// ---------------- kernel 5: grouped GU GEMM + SiLU ----------------
// C_g[m,n] = sum_k x[tok(m),k] * gup[e, n, k],  C_u with rows n+IDIM
// h[p, n] = silu(C_g) * C_u
#define BM 64
#define BN 64
#define BK 16

__global__ __launch_bounds__(256) void gu_kernel(
    const float* __restrict__ x, const float* __restrict__ gup)
{
    int e = blockIdx.z;
    int seg0 = g_segstart[e];
    int cnt  = g_segstart[e + 1] - seg0;
    int m0 = blockIdx.x * BM;
    if (m0 >= cnt) return;
    int n0 = blockIdx.y * BN;          // h-column tile base, 0..IDIM
    int tid = threadIdx.x;

    __shared__ float As[BK][BM + 4];
    __shared__ float Bg[BK][BN + 4];
    __shared__ float Bu[BK][BN + 4];

    int lm = tid >> 2;                 // 0..63
    int k4 = (tid & 3) * 4;            // 0,4,8,12

    int tok = (m0 + lm < cnt) ? g_pair_token[seg0 + m0 + lm] : g_pair_token[seg0];
    const float* arow  = x   + (size_t)tok * HDIM;
    const float* bgrow = gup + (size_t)e * TWO_I * HDIM + (size_t)(n0 + lm) * HDIM;
    const float* burow = gup + (size_t)e * TWO_I * HDIM + (size_t)(IDIM + n0 + lm) * HDIM;

    int tx = tid & 15;                 // n sub-tile
    int ty = tid >> 4;                 // m sub-tile
    float cg[4][4] = {}, cu[4][4] = {};

    for (int k0 = 0; k0 < HDIM; k0 += BK) {
        float4 av = *(const float4*)(arow  + k0 + k4);
        float4 gv = *(const float4*)(bgrow + k0 + k4);
        float4 uv = *(const float4*)(burow + k0 + k4);
        __syncthreads();
        As[k4 + 0][lm] = av.x; As[k4 + 1][lm] = av.y; As[k4 + 2][lm] = av.z; As[k4 + 3][lm] = av.w;
        Bg[k4 + 0][lm] = gv.x; Bg[k4 + 1][lm] = gv.y; Bg[k4 + 2][lm] = gv.z; Bg[k4 + 3][lm] = gv.w;
        Bu[k4 + 0][lm] = uv.x; Bu[k4 + 1][lm] = uv.y; Bu[k4 + 2][lm] = uv.z; Bu[k4 + 3][lm] = uv.w;
        __syncthreads();
#pragma unroll
        for (int k = 0; k < BK; k++) {
            float a[4], bg[4], bu[4];
#pragma unroll
            for (int i = 0; i < 4; i++) a[i] = As[k][ty * 4 + i];
#pragma unroll
            for (int j = 0; j < 4; j++) { bg[j] = Bg[k][tx * 4 + j]; bu[j] = Bu[k][tx * 4 + j]; }
#pragma unroll
            for (int i = 0; i < 4; i++)
#pragma unroll
                for (int j = 0; j < 4; j++) {
                    cg[i][j] += a[i] * bg[j];
                    cu[i][j] += a[i] * bu[j];
                }
        }
    }

#pragma unroll
    for (int i = 0; i < 4; i++) {
        int m = ty * 4 + i;
        if (m0 + m >= cnt) continue;
        float* hrow = g_h + (size_t)(seg0 + m0 + m) * IDIM + n0;
#pragma unroll
        for (int j = 0; j < 4; j++) {
            float g = cg[i][j], u = cu[i][j];
            float h = (g / (1.f + expf(-g))) * u;   // silu(g) * u
            hrow[tx * 4 + j] = h;
        }
    }
}

// ---------------- kernel 6: grouped down GEMM + weighted scatter-add ----------------
// out[tok(m), n] += w(m) * sum_i h[p(m), i] * dw[e, n, i]
__global__ __launch_bounds__(256) void down_kernel(
    const float* __restrict__ dw, float* __restrict__ out)
{
    int e = blockIdx.z;
    int seg0 = g_segstart[e];
    int cnt  = g_segstart[e + 1] - seg0;
    int m0 = blockIdx.x * BM;
    if (m0 >= cnt) return;
    int n0 = blockIdx.y * BN;          // H-column tile base
    int tid = threadIdx.x;

    __shared__ float As[BK][BM + 4];
    __shared__ float Bs[BK][BN + 4];

    int lm = tid >> 2;
    int k4 = (tid & 3) * 4;

    int mrow = (m0 + lm < cnt) ? (m0 + lm) : 0;
    const float* arow = g_h + (size_t)(seg0 + mrow) * IDIM;
    const float* brow = dw  + (size_t)e * HDIM * IDIM + (size_t)(n0 + lm) * IDIM;

    int tx = tid & 15;
    int ty = tid >> 4;
    float c[4][4] = {};

    for (int k0 = 0; k0 < IDIM; k0 += BK) {
        float4 av = *(const float4*)(arow + k0 + k4);
        float4 bv = *(const float4*)(brow + k0 + k4);
        __syncthreads();
        As[k4 + 0][lm] = av.x; As[k4 + 1][lm] = av.y; As[k4 + 2][lm] = av.z; As[k4 + 3][lm] = av.w;
        Bs[k4 + 0][lm] = bv.x; Bs[k4 + 1][lm] = bv.y; Bs[k4 + 2][lm] = bv.z; Bs[k4 + 3][lm] = bv.w;
        __syncthreads();
#pragma unroll
        for (int k = 0; k < BK; k++) {
            float a[4], b[4];
#pragma unroll
            for (int i = 0; i < 4; i++) a[i] = As[k][ty * 4 + i];
#pragma unroll
            for (int j = 0; j < 4; j++) b[j] = Bs[k][tx * 4 + j];
#pragma unroll
            for (int i = 0; i < 4; i++)
#pragma unroll
                for (int j = 0; j < 4; j++) c[i][j] += a[i] * b[j];
        }
    }

#pragma unroll
    for (int i = 0; i < 4; i++) {
        int m = ty * 4 + i;
        if (m0 + m >= cnt) continue;
        int p = seg0 + m0 + m;
        int t = g_pair_token[p];
        float w = g_pair_w[p];
        float* orow = out + (size_t)t * HDIM + n0;
#pragma unroll
        for (int j = 0; j < 4; j++)
            atomicAdd(&orow[tx * 4 + j], w * c[i][j]);   // exactly 2 adds/elem -> deterministic
    }
}

// ---------------- launch ----------------
extern "C" void kernel_launch(void* const* d_in, const int* in_sizes, int n_in,
                              void* d_out, int out_size)
{
    const float* x   = (const float*)d_in[0];  // [T, H]
    const float* gw  = (const float*)d_in[1];  // [E, H]
    const float* gup = (const float*)d_in[2];  // [E, 2I, H]
    const float* dw  = (const float*)d_in[3];  // [E, H, I]
    float* out = (float*)d_out;

    int T = in_sizes[0] / HDIM;                // 2048
    size_t main_sz = (size_t)T * HDIM;

    // router_logits is the second tuple output; write it after `out` if the
    // harness allotted space, else into fallback scratch.
    float* logits;
    if ((size_t)out_size >= main_sz + (size_t)T * NEXP) {
        logits = out + main_sz;
    } else {
        cudaGetSymbolAddress((void**)&logits, g_logits_fallback);
    }

    init_kernel<<<1, 32>>>();
    router_kernel<<<T, 128>>>(x, gw, logits, T);
    offsets_kernel<<<1, 32>>>();
    dispatch_kernel<<<(T + 127) / 128, 128>>>(T);

    size_t n4 = main_sz / 4;
    zero_kernel<<<(int)((n4 + 255) / 256), 256>>>(out, n4);

    int mtiles = (T + BM - 1) / BM;   // a segment can hold at most T pairs
    dim3 gu_grid(mtiles, IDIM / BN, NEXP);
    gu_kernel<<<gu_grid, 256>>>(x, gup);

    dim3 dn_grid(mtiles, HDIM / BN, NEXP);
    down_kernel<<<dn_grid, 256>>>(dw, out);
}

// round 3
// speedup vs baseline: 1.8799x; 1.8799x over previous
#include <cuda_runtime.h>
#include <cuda_bf16.h>
#include <math.h>
#include <stdint.h>

#define HDIM 2048
#define NEXP 16
#define IDIM 768
#define TWO_I 1536
#define TMAX 2048
#define PMAX (TMAX*2)

// ---------------- device scratch ----------------
__device__ int   g_count[NEXP];
__device__ int   g_cursor[NEXP];
__device__ int   g_segstart[NEXP + 1];
__device__ int   g_tok_e[TMAX * 2];
__device__ float g_tok_w[TMAX * 2];
__device__ int   g_pair_token[PMAX];
__device__ int   g_tok_pair[TMAX * 2];
__device__ __align__(16) float g_gu[(size_t)PMAX * TWO_I];   // raw gate_up output
__device__ __align__(16) float g_h[(size_t)PMAX * IDIM];     // SwiGLU activations
__device__ __align__(16) float g_y[(size_t)PMAX * HDIM];     // down-proj per pair
__device__ float g_logits_fallback[TMAX * NEXP];

// ---------------- portable PTX helpers ----------------
__device__ __forceinline__ uint32_t smem_u32(const void* p) {
    uint32_t a;
    asm("{ .reg .u64 t; cvta.to.shared.u64 t, %1; cvt.u32.u64 %0, t; }" : "=r"(a) : "l"(p));
    return a;
}
#define LDMX4(r, addr) \
    asm volatile("ldmatrix.sync.aligned.m8n8.x4.shared.b16 {%0,%1,%2,%3}, [%4];" \
        : "=r"((r)[0]), "=r"((r)[1]), "=r"((r)[2]), "=r"((r)[3]) : "r"(addr))
#define MMA(acc, a, b0, b1) \
    asm volatile("mma.sync.aligned.m16n8k16.row.col.f32.bf16.bf16.f32 " \
        "{%0,%1,%2,%3}, {%4,%5,%6,%7}, {%8,%9}, {%0,%1,%2,%3};" \
        : "+f"((acc)[0]), "+f"((acc)[1]), "+f"((acc)[2]), "+f"((acc)[3]) \
        : "r"((a)[0]), "r"((a)[1]), "r"((a)[2]), "r"((a)[3]), "r"(b0), "r"(b1))
#define STSV2(addr, x, y) \
    asm volatile("st.shared.v2.b32 [%0], {%1,%2};" :: "r"((uint32_t)(addr)), "r"(x), "r"(y) : "memory")

// XOR swizzle for 64B-pitch rows: conflict-free ldmatrix + STS
__device__ __forceinline__ uint32_t swz(uint32_t row, uint32_t colbyte) {
    return (row * 64 + colbyte) ^ ((row & 6) << 3);
}

// split fp32 v into bf16 hi + bf16 lo (lo = rn(v - hi))
__device__ __forceinline__ void bf16split(float4 v, uint32_t& h01, uint32_t& h23,
                                          uint32_t& l01, uint32_t& l23) {
    __nv_bfloat16 hx = __float2bfloat16_rn(v.x);
    __nv_bfloat16 hy = __float2bfloat16_rn(v.y);
    __nv_bfloat16 hz = __float2bfloat16_rn(v.z);
    __nv_bfloat16 hw = __float2bfloat16_rn(v.w);
    __nv_bfloat16 lx = __float2bfloat16_rn(v.x - __bfloat162float(hx));
    __nv_bfloat16 ly = __float2bfloat16_rn(v.y - __bfloat162float(hy));
    __nv_bfloat16 lz = __float2bfloat16_rn(v.z - __bfloat162float(hz));
    __nv_bfloat16 lw = __float2bfloat16_rn(v.w - __bfloat162float(hw));
    h01 = (uint32_t)__bfloat16_as_ushort(hx) | ((uint32_t)__bfloat16_as_ushort(hy) << 16);
    h23 = (uint32_t)__bfloat16_as_ushort(hz) | ((uint32_t)__bfloat16_as_ushort(hw) << 16);
    l01 = (uint32_t)__bfloat16_as_ushort(lx) | ((uint32_t)__bfloat16_as_ushort(ly) << 16);
    l23 = (uint32_t)__bfloat16_as_ushort(lz) | ((uint32_t)__bfloat16_as_ushort(lw) << 16);
}

// ---------------- small kernels ----------------
__global__ void init_kernel() { int i = threadIdx.x; if (i < NEXP) g_count[i] = 0; }

__global__ __launch_bounds__(128) void router_kernel(
    const float* __restrict__ x, const float* __restrict__ gw, float* __restrict__ logits, int T)
{
    int t = blockIdx.x, tid = threadIdx.x;
    float acc[NEXP];
#pragma unroll
    for (int e = 0; e < NEXP; e++) acc[e] = 0.f;
    const float* xr = x + (size_t)t * HDIM;
    for (int h = tid; h < HDIM; h += 128) {
        float xv = xr[h];
#pragma unroll
        for (int e = 0; e < NEXP; e++) acc[e] += xv * gw[e * HDIM + h];
    }
#pragma unroll
    for (int e = 0; e < NEXP; e++)
#pragma unroll
        for (int off = 16; off > 0; off >>= 1) acc[e] += __shfl_down_sync(0xffffffffu, acc[e], off);
    __shared__ float sred[4][NEXP];
    __shared__ float slog[NEXP];
    int warp = tid >> 5, lane = tid & 31;
    if (lane == 0)
#pragma unroll
        for (int e = 0; e < NEXP; e++) sred[warp][e] = acc[e];
    __syncthreads();
    if (tid < NEXP) {
        float v = sred[0][tid] + sred[1][tid] + sred[2][tid] + sred[3][tid];
        slog[tid] = v;
        logits[t * NEXP + tid] = v;
    }
    __syncthreads();
    if (tid == 0) {
        int i0 = 0; float v0 = slog[0];
#pragma unroll
        for (int e = 1; e < NEXP; e++) if (slog[e] > v0) { v0 = slog[e]; i0 = e; }
        int i1 = -1; float v1 = -INFINITY;
#pragma unroll
        for (int e = 0; e < NEXP; e++) { if (e == i0) continue; if (slog[e] > v1) { v1 = slog[e]; i1 = e; } }
        float e1 = expf(v1 - v0);
        float inv = 1.f / (1.f + e1);
        g_tok_e[t * 2 + 0] = i0; g_tok_w[t * 2 + 0] = inv;
        g_tok_e[t * 2 + 1] = i1; g_tok_w[t * 2 + 1] = e1 * inv;
        atomicAdd(&g_count[i0], 1);
        atomicAdd(&g_count[i1], 1);
    }
}

__global__ void offsets_kernel() {
    if (threadIdx.x == 0) {
        int off = 0;
#pragma unroll
        for (int e = 0; e < NEXP; e++) { g_segstart[e] = off; off += g_count[e]; g_cursor[e] = 0; }
        g_segstart[NEXP] = off;
    }
}

__global__ void dispatch_kernel(int T) {
    int t = blockIdx.x * blockDim.x + threadIdx.x;
    if (t >= T) return;
#pragma unroll
    for (int s = 0; s < 2; s++) {
        int e = g_tok_e[t * 2 + s];
        int pos = g_segstart[e] + atomicAdd(&g_cursor[e], 1);
        g_pair_token[pos] = t;
        g_tok_pair[t * 2 + s] = pos;
    }
}

// ---------------- grouped GEMM: C[m,n] = sum_k A[row(m),k] * B[e,n,k] ----------------
// bf16x3 split on tensor cores. BM=128, BN=128, BK=32, 8 warps (2m x 4n), warp tile 64x32.
#define GSMEM 65536   // 2 stages x (A_hi,A_lo,B_hi,B_lo) x 8KB

template<int KDIM, bool GATHER>
__global__ __launch_bounds__(256, 1) void gemm_kernel(
    const float* __restrict__ A, const float* __restrict__ B,
    float* __restrict__ C, int ldc, size_t b_expert_stride)
{
    int e = blockIdx.z;
    int seg0 = g_segstart[e];
    int cnt  = g_segstart[e + 1] - seg0;
    int m0 = blockIdx.x * 128;
    if (m0 >= cnt) return;
    int n0 = blockIdx.y * 128;

    extern __shared__ char smem[];
    uint32_t sbase = smem_u32(smem);

    int tid = threadIdx.x;
    int lane = tid & 31, wid = tid >> 5;
    int warp_m = wid >> 2;        // 0..1
    int warp_n = wid & 3;         // 0..3

    // -------- loader setup: thread -> (row, 16-col half) of both A and B tiles --------
    int row  = tid >> 1;          // 0..127
    int half = tid & 1;
    int mrow = m0 + row; if (mrow >= cnt) mrow = cnt - 1;
    int arow = GATHER ? g_pair_token[seg0 + mrow] : (seg0 + mrow);
    const float* aptr = A + (size_t)arow * KDIM + half * 16;
    const float* bptr = B + (size_t)e * b_expert_stride + (size_t)(n0 + row) * KDIM + half * 16;

    uint32_t sts_off[4];
#pragma unroll
    for (int j = 0; j < 4; j++) sts_off[j] = swz((uint32_t)row, (uint32_t)(half * 32 + j * 8));

    // -------- ldmatrix per-thread address offsets --------
    int a_r = lane & 15;
    int a_k = lane >> 4;                       // 0/1
    int b_n = (lane & 7) + ((lane & 16) ? 8 : 0);
    int b_k = (lane & 8) ? 1 : 0;

    uint32_t a_off[4][2], b_off[2][2];
#pragma unroll
    for (int mf = 0; mf < 4; mf++)
#pragma unroll
        for (int kk = 0; kk < 2; kk++) {
            uint32_t r = warp_m * 64 + mf * 16 + a_r;
            a_off[mf][kk] = swz(r, (uint32_t)((kk * 2 + a_k) * 16));
        }
#pragma unroll
    for (int nf = 0; nf < 2; nf++)
#pragma unroll
        for (int kk = 0; kk < 2; kk++) {
            uint32_t r = warp_n * 32 + nf * 16 + b_n;
            b_off[nf][kk] = swz(r, (uint32_t)((kk * 2 + b_k) * 16));
        }

    float acc[4][4][4];
#pragma unroll
    for (int mf = 0; mf < 4; mf++)
#pragma unroll
        for (int j = 0; j < 4; j++)
#pragma unroll
            for (int q = 0; q < 4; q++) acc[mf][j][q] = 0.f;

    const int NCH = KDIM / 32;
    float4 pa[4], pb[4];

    // prologue: chunk 0 -> stage 0
#pragma unroll
    for (int j = 0; j < 4; j++) {
        pa[j] = ((const float4*)aptr)[j];
        pb[j] = ((const float4*)bptr)[j];
    }
    {
        uint32_t sb = sbase;
#pragma unroll
        for (int j = 0; j < 4; j++) {
            uint32_t h01, h23, l01, l23;
            bf16split(pa[j], h01, h23, l01, l23);
            STSV2(sb + sts_off[j], h01, h23);
            STSV2(sb + 8192 + sts_off[j], l01, l23);
            bf16split(pb[j], h01, h23, l01, l23);
            STSV2(sb + 16384 + sts_off[j], h01, h23);
            STSV2(sb + 24576 + sts_off[j], l01, l23);
        }
    }
    __syncthreads();

#pragma unroll 1
    for (int ch = 0; ch < NCH; ch++) {
        uint32_t sb = sbase + (ch & 1) * 32768;
        if (ch + 1 < NCH) {
            const float* ap = aptr + (ch + 1) * 32;
            const float* bp = bptr + (ch + 1) * 32;
#pragma unroll
            for (int j = 0; j < 4; j++) {
                pa[j] = ((const float4*)ap)[j];
                pb[j] = ((const float4*)bp)[j];
            }
        }
#pragma unroll
        for (int kk = 0; kk < 2; kk++) {
            uint32_t ahf[4][4], alf[4][4], bhf[2][4], blf[2][4];
#pragma unroll
            for (int mf = 0; mf < 4; mf++) {
                LDMX4(ahf[mf], sb + a_off[mf][kk]);
                LDMX4(alf[mf], sb + 8192 + a_off[mf][kk]);
            }
#pragma unroll
            for (int nf = 0; nf < 2; nf++) {
                LDMX4(bhf[nf], sb + 16384 + b_off[nf][kk]);
                LDMX4(blf[nf], sb + 24576 + b_off[nf][kk]);
            }
#pragma unroll
            for (int mf = 0; mf < 4; mf++)
#pragma unroll
                for (int j = 0; j < 4; j++) {
                    uint32_t b0h = bhf[j >> 1][(j & 1) * 2], b1h = bhf[j >> 1][(j & 1) * 2 + 1];
                    uint32_t b0l = blf[j >> 1][(j & 1) * 2], b1l = blf[j >> 1][(j & 1) * 2 + 1];
                    MMA(acc[mf][j], ahf[mf], b0h, b1h);
                    MMA(acc[mf][j], alf[mf], b0h, b1h);
                    MMA(acc[mf][j], ahf[mf], b0l, b1l);
                }
        }
        if (ch + 1 < NCH) {
            __syncthreads();
            uint32_t sb2 = sbase + ((ch + 1) & 1) * 32768;
#pragma unroll
            for (int j = 0; j < 4; j++) {
                uint32_t h01, h23, l01, l23;
                bf16split(pa[j], h01, h23, l01, l23);
                STSV2(sb2 + sts_off[j], h01, h23);
                STSV2(sb2 + 8192 + sts_off[j], l01, l23);
                bf16split(pb[j], h01, h23, l01, l23);
                STSV2(sb2 + 16384 + sts_off[j], h01, h23);
                STSV2(sb2 + 24576 + sts_off[j], l01, l23);
            }
            __syncthreads();
        }
    }

    // -------- epilogue --------
    int erow = lane >> 2;
    int ecol = (lane & 3) * 2;
#pragma unroll
    for (int mf = 0; mf < 4; mf++) {
        int mloc0 = m0 + warp_m * 64 + mf * 16 + erow;
        int mloc1 = mloc0 + 8;
#pragma unroll
        for (int j = 0; j < 4; j++) {
            int nglob = n0 + warp_n * 32 + j * 8 + ecol;
            if (mloc0 < cnt) {
                float2 v = make_float2(acc[mf][j][0], acc[mf][j][1]);
                *(float2*)(C + (size_t)(seg0 + mloc0) * ldc + nglob) = v;
            }
            if (mloc1 < cnt) {
                float2 v = make_float2(acc[mf][j][2], acc[mf][j][3]);
                *(float2*)(C + (size_t)(seg0 + mloc1) * ldc + nglob) = v;
            }
        }
    }
}

// ---------------- SwiGLU elementwise ----------------
__global__ __launch_bounds__(256) void swiglu_kernel(int npairs)
{
    int idx = blockIdx.x * blockDim.x + threadIdx.x;
    if (idx >= npairs * (IDIM / 4)) return;
    int p = idx / (IDIM / 4);
    int c = idx % (IDIM / 4);
    float4 g4 = ((const float4*)g_gu)[(size_t)p * (TWO_I / 4) + c];
    float4 u4 = ((const float4*)g_gu)[(size_t)p * (TWO_I / 4) + (IDIM / 4) + c];
    float4 h;
    h.x = u4.x * g4.x / (1.f + expf(-g4.x));
    h.y = u4.y * g4.y / (1.f + expf(-g4.y));
    h.z = u4.z * g4.z / (1.f + expf(-g4.z));
    h.w = u4.w * g4.w / (1.f + expf(-g4.w));
    ((float4*)g_h)[(size_t)p * (IDIM / 4) + c] = h;
}

// ---------------- combine: out[t] = w0*y[p0] + w1*y[p1] ----------------
__global__ __launch_bounds__(256) void combine_kernel(float* __restrict__ out, int T)
{
    int idx = blockIdx.x * blockDim.x + threadIdx.x;
    if (idx >= T * (HDIM / 4)) return;
    int t = idx >> 9;            // HDIM/4 = 512
    int c = idx & 511;
    int p0 = g_tok_pair[2 * t], p1 = g_tok_pair[2 * t + 1];
    float w0 = g_tok_w[2 * t], w1 = g_tok_w[2 * t + 1];
    float4 a = ((const float4*)g_y)[(size_t)p0 * 512 + c];
    float4 b = ((const float4*)g_y)[(size_t)p1 * 512 + c];
    float4 o;
    o.x = w0 * a.x + w1 * b.x;
    o.y = w0 * a.y + w1 * b.y;
    o.z = w0 * a.z + w1 * b.z;
    o.w = w0 * a.w + w1 * b.w;
    ((float4*)out)[idx] = o;
}

// ---------------- launch ----------------
extern "C" void kernel_launch(void* const* d_in, const int* in_sizes, int n_in,
                              void* d_out, int out_size)
{
    const float* x   = (const float*)d_in[0];
    const float* gw  = (const float*)d_in[1];
    const float* gup = (const float*)d_in[2];
    const float* dw  = (const float*)d_in[3];
    float* out = (float*)d_out;

    int T = in_sizes[0] / HDIM;
    size_t main_sz = (size_t)T * HDIM;

    float* logits;
    if ((size_t)out_size >= main_sz + (size_t)T * NEXP) logits = out + main_sz;
    else cudaGetSymbolAddress((void**)&logits, g_logits_fallback);

    cudaFuncSetAttribute((const void*)gemm_kernel<HDIM, true>,
                         cudaFuncAttributeMaxDynamicSharedMemorySize, GSMEM);
    cudaFuncSetAttribute((const void*)gemm_kernel<IDIM, false>,
                         cudaFuncAttributeMaxDynamicSharedMemorySize, GSMEM);

    init_kernel<<<1, 32>>>();
    router_kernel<<<T, 128>>>(x, gw, logits, T);
    offsets_kernel<<<1, 32>>>();
    dispatch_kernel<<<(T + 127) / 128, 128>>>(T);

    int mtiles = (T + 127) / 128;

    float* d_gu; cudaGetSymbolAddress((void**)&d_gu, g_gu);
    float* d_h;  cudaGetSymbolAddress((void**)&d_h,  g_h);
    float* d_y;  cudaGetSymbolAddress((void**)&d_y,  g_y);

    dim3 gu_grid(mtiles, TWO_I / 128, NEXP);
    gemm_kernel<HDIM, true><<<gu_grid, 256, GSMEM>>>(x, gup, d_gu, TWO_I, (size_t)TWO_I * HDIM);

    int npairs = 2 * T;
    swiglu_kernel<<<(npairs * (IDIM / 4) + 255) / 256, 256>>>(npairs);

    dim3 dn_grid(mtiles, HDIM / 128, NEXP);
    gemm_kernel<IDIM, false><<<dn_grid, 256, GSMEM>>>(d_h, dw, d_y, HDIM, (size_t)HDIM * IDIM);

    combine_kernel<<<(T * (HDIM / 4) + 255) / 256, 256>>>(out, T);
}

// round 4
// speedup vs baseline: 2.4483x; 1.3024x over previous
#include <cuda_runtime.h>
#include <cuda_bf16.h>
#include <math.h>
#include <stdint.h>

#define HDIM 2048
#define NEXP 16
#define IDIM 768
#define TWO_I 1536
#define TMAX 2048
#define PMAX (TMAX*2)

typedef unsigned short ushort_t;

// ---------------- device scratch ----------------
__device__ int   g_count[NEXP];
__device__ int   g_cursor[NEXP];
__device__ int   g_segstart[NEXP + 1];
__device__ int   g_tok_e[TMAX * 2];
__device__ float g_tok_w[TMAX * 2];
__device__ int   g_pair_token[PMAX];
__device__ int   g_tok_pair[TMAX * 2];
__device__ __align__(16) float    g_gu[(size_t)PMAX * TWO_I];    // raw gate_up output
__device__ __align__(16) ushort_t g_h_hi[(size_t)PMAX * IDIM];   // h split: bf16 hi
__device__ __align__(16) ushort_t g_h_lo[(size_t)PMAX * IDIM];   // h split: bf16 lo
__device__ __align__(16) float    g_y[(size_t)PMAX * HDIM];      // down-proj per pair
__device__ float g_logits_fallback[TMAX * NEXP];

// ---------------- portable PTX helpers ----------------
__device__ __forceinline__ uint32_t smem_u32(const void* p) {
    uint32_t a;
    asm("{ .reg .u64 t; cvta.to.shared.u64 t, %1; cvt.u32.u64 %0, t; }" : "=r"(a) : "l"(p));
    return a;
}
#define LDMX4(r, addr) \
    asm volatile("ldmatrix.sync.aligned.m8n8.x4.shared.b16 {%0,%1,%2,%3}, [%4];" \
        : "=r"((r)[0]), "=r"((r)[1]), "=r"((r)[2]), "=r"((r)[3]) : "r"(addr))
#define MMA(acc, a, b0, b1) \
    asm volatile("mma.sync.aligned.m16n8k16.row.col.f32.bf16.bf16.f32 " \
        "{%0,%1,%2,%3}, {%4,%5,%6,%7}, {%8,%9}, {%0,%1,%2,%3};" \
        : "+f"((acc)[0]), "+f"((acc)[1]), "+f"((acc)[2]), "+f"((acc)[3]) \
        : "r"((a)[0]), "r"((a)[1]), "r"((a)[2]), "r"((a)[3]), "r"(b0), "r"(b1))
#define STSV2(addr, x, y) \
    asm volatile("st.shared.v2.b32 [%0], {%1,%2};" :: "r"((uint32_t)(addr)), "r"(x), "r"(y) : "memory")
#define STSV4(addr, x, y, z, w) \
    asm volatile("st.shared.v4.b32 [%0], {%1,%2,%3,%4};" :: "r"((uint32_t)(addr)), \
        "r"(x), "r"(y), "r"(z), "r"(w) : "memory")

// XOR swizzle for 64B-pitch rows (16B-granular XOR: keeps 16B alignment)
__device__ __forceinline__ uint32_t swz(uint32_t row, uint32_t colbyte) {
    return (row * 64 + colbyte) ^ ((row & 6) << 3);
}

// packed split: {x,y} fp32 -> bf16x2 hi + bf16x2 lo (x in low half)
__device__ __forceinline__ void split2(float x, float y, uint32_t& hi, uint32_t& lo) {
    uint32_t h;
    asm("cvt.rn.bf16x2.f32 %0, %1, %2;" : "=r"(h) : "f"(y), "f"(x));
    float hx = __uint_as_float(h << 16);
    float hy = __uint_as_float(h & 0xffff0000u);
    float lx = x - hx, ly = y - hy;
    uint32_t l;
    asm("cvt.rn.bf16x2.f32 %0, %1, %2;" : "=r"(l) : "f"(ly), "f"(lx));
    hi = h; lo = l;
}
__device__ __forceinline__ void split4(float4 v, uint32_t& h01, uint32_t& h23,
                                       uint32_t& l01, uint32_t& l23) {
    split2(v.x, v.y, h01, l01);
    split2(v.z, v.w, h23, l23);
}

// ---------------- small kernels ----------------
__global__ void init_kernel() { int i = threadIdx.x; if (i < NEXP) g_count[i] = 0; }

__global__ __launch_bounds__(128) void router_kernel(
    const float* __restrict__ x, const float* __restrict__ gw, float* __restrict__ logits, int T)
{
    int t = blockIdx.x, tid = threadIdx.x;
    float acc[NEXP];
#pragma unroll
    for (int e = 0; e < NEXP; e++) acc[e] = 0.f;
    const float* xr = x + (size_t)t * HDIM;
    for (int h = tid; h < HDIM; h += 128) {
        float xv = xr[h];
#pragma unroll
        for (int e = 0; e < NEXP; e++) acc[e] += xv * gw[e * HDIM + h];
    }
#pragma unroll
    for (int e = 0; e < NEXP; e++)
#pragma unroll
        for (int off = 16; off > 0; off >>= 1) acc[e] += __shfl_down_sync(0xffffffffu, acc[e], off);
    __shared__ float sred[4][NEXP];
    __shared__ float slog[NEXP];
    int warp = tid >> 5, lane = tid & 31;
    if (lane == 0)
#pragma unroll
        for (int e = 0; e < NEXP; e++) sred[warp][e] = acc[e];
    __syncthreads();
    if (tid < NEXP) {
        float v = sred[0][tid] + sred[1][tid] + sred[2][tid] + sred[3][tid];
        slog[tid] = v;
        logits[t * NEXP + tid] = v;
    }
    __syncthreads();
    if (tid == 0) {
        int i0 = 0; float v0 = slog[0];
#pragma unroll
        for (int e = 1; e < NEXP; e++) if (slog[e] > v0) { v0 = slog[e]; i0 = e; }
        int i1 = -1; float v1 = -INFINITY;
#pragma unroll
        for (int e = 0; e < NEXP; e++) { if (e == i0) continue; if (slog[e] > v1) { v1 = slog[e]; i1 = e; } }
        float e1 = expf(v1 - v0);
        float inv = 1.f / (1.f + e1);
        g_tok_e[t * 2 + 0] = i0; g_tok_w[t * 2 + 0] = inv;
        g_tok_e[t * 2 + 1] = i1; g_tok_w[t * 2 + 1] = e1 * inv;
        atomicAdd(&g_count[i0], 1);
        atomicAdd(&g_count[i1], 1);
    }
}

__global__ void offsets_kernel() {
    if (threadIdx.x == 0) {
        int off = 0;
#pragma unroll
        for (int e = 0; e < NEXP; e++) { g_segstart[e] = off; off += g_count[e]; g_cursor[e] = 0; }
        g_segstart[NEXP] = off;
    }
}

__global__ void dispatch_kernel(int T) {
    int t = blockIdx.x * blockDim.x + threadIdx.x;
    if (t >= T) return;
#pragma unroll
    for (int s = 0; s < 2; s++) {
        int e = g_tok_e[t * 2 + s];
        int pos = g_segstart[e] + atomicAdd(&g_cursor[e], 1);
        g_pair_token[pos] = t;
        g_tok_pair[t * 2 + s] = pos;
    }
}

// ---------------- grouped GEMM (bf16x3 split, mma.sync) ----------------
// C[m,n] = sum_k A[row(m),k] * B[e,n,k]; BM=BN=128, BK=32, 8 warps (2m x 4n).
// Stage layout: A_hi 0 | A_lo 8K | B_hi 16K | B_lo 24K, 2 stages = 64KB.
#define GSMEM 65536
#define STAGE 32768

// AKIND: 0 = A fp32 gathered by pair_token (gu); 1 = A pre-split bf16 (down)
template<int KDIM, int AKIND>
__global__ __launch_bounds__(256, 1) void gemm2(
    const float* __restrict__ Af32, const float* __restrict__ B,
    float* __restrict__ C, int ldc, size_t b_expert_stride)
{
    int e = blockIdx.z;
    int seg0 = g_segstart[e];
    int cnt  = g_segstart[e + 1] - seg0;
    int m0 = blockIdx.x * 128;
    if (m0 >= cnt) return;
    int n0 = blockIdx.y * 128;

    extern __shared__ char smem[];
    uint32_t sbase = smem_u32(smem);

    int tid = threadIdx.x;
    int lane = tid & 31, wid = tid >> 5;
    int warp_m = wid >> 2;
    int warp_n = wid & 3;

    // -------- loader setup --------
    int row  = tid >> 1;          // 0..127
    int half = tid & 1;
    int mrow = m0 + row; if (mrow >= cnt) mrow = cnt - 1;

    const float*    aptr = nullptr;
    const uint4*    ahip = nullptr;
    const uint4*    alop = nullptr;
    if (AKIND == 0) {
        int arow = g_pair_token[seg0 + mrow];
        aptr = Af32 + (size_t)arow * KDIM + half * 16;
    } else {
        ahip = (const uint4*)(g_h_hi + (size_t)(seg0 + mrow) * IDIM) + half * 2;
        alop = (const uint4*)(g_h_lo + (size_t)(seg0 + mrow) * IDIM) + half * 2;
    }
    const float* bptr = B + (size_t)e * b_expert_stride + (size_t)(n0 + row) * KDIM + half * 16;

    uint32_t sts8[4], sts16[2];
#pragma unroll
    for (int j = 0; j < 4; j++) sts8[j] = swz((uint32_t)row, (uint32_t)(half * 32 + j * 8));
#pragma unroll
    for (int j = 0; j < 2; j++) sts16[j] = swz((uint32_t)row, (uint32_t)(half * 32 + j * 16));

    // -------- ldmatrix offsets --------
    int a_r = lane & 15;
    int a_k = lane >> 4;
    int b_n = (lane & 7) + ((lane & 16) ? 8 : 0);
    int b_k = (lane & 8) ? 1 : 0;

    uint32_t a_off[4][2], b_off[2][2];
#pragma unroll
    for (int mf = 0; mf < 4; mf++)
#pragma unroll
        for (int kk = 0; kk < 2; kk++)
            a_off[mf][kk] = swz((uint32_t)(warp_m * 64 + mf * 16 + a_r), (uint32_t)((kk * 2 + a_k) * 16));
#pragma unroll
    for (int nf = 0; nf < 2; nf++)
#pragma unroll
        for (int kk = 0; kk < 2; kk++)
            b_off[nf][kk] = swz((uint32_t)(warp_n * 32 + nf * 16 + b_n), (uint32_t)((kk * 2 + b_k) * 16));

    float acc[4][4][4];
#pragma unroll
    for (int mf = 0; mf < 4; mf++)
#pragma unroll
        for (int j = 0; j < 4; j++)
#pragma unroll
            for (int q = 0; q < 4; q++) acc[mf][j][q] = 0.f;

    const int NCH = KDIM / 32;

    // prefetch registers
    float4 pa[4], pb[4];
    uint4  pah[2], pal[2];

    // ---- LDG chunk c -> regs ----
    auto ldg_chunk = [&](int c) {
        const float* bp = bptr + c * 32;
#pragma unroll
        for (int j = 0; j < 4; j++) pb[j] = ((const float4*)bp)[j];
        if (AKIND == 0) {
            const float* ap = aptr + c * 32;
#pragma unroll
            for (int j = 0; j < 4; j++) pa[j] = ((const float4*)ap)[j];
        } else {
#pragma unroll
            for (int j = 0; j < 2; j++) { pah[j] = ahip[c * 4 + j]; pal[j] = alop[c * 4 + j]; }
        }
    };
    // ---- convert + STS regs -> stage buffer ----
    auto sts_chunk = [&](uint32_t sb) {
        if (AKIND == 0) {
#pragma unroll
            for (int j = 0; j < 4; j++) {
                uint32_t h01, h23, l01, l23;
                split4(pa[j], h01, h23, l01, l23);
                STSV2(sb + sts8[j],        h01, h23);
                STSV2(sb + 8192 + sts8[j], l01, l23);
            }
        } else {
#pragma unroll
            for (int j = 0; j < 2; j++) {
                STSV4(sb + sts16[j],        pah[j].x, pah[j].y, pah[j].z, pah[j].w);
                STSV4(sb + 8192 + sts16[j], pal[j].x, pal[j].y, pal[j].z, pal[j].w);
            }
        }
#pragma unroll
        for (int j = 0; j < 4; j++) {
            uint32_t h01, h23, l01, l23;
            split4(pb[j], h01, h23, l01, l23);
            STSV2(sb + 16384 + sts8[j], h01, h23);
            STSV2(sb + 24576 + sts8[j], l01, l23);
        }
    };

    // prologue: chunk0 -> buf0, prefetch chunk1
    ldg_chunk(0);
    sts_chunk(sbase);
    ldg_chunk(1);
    __syncthreads();

#pragma unroll 2
    for (int ch = 0; ch < NCH; ch++) {
        uint32_t sb  = sbase + (ch & 1) * STAGE;
        uint32_t sbn = sbase + ((ch + 1) & 1) * STAGE;
        if (ch + 1 < NCH) sts_chunk(sbn);          // fill other buffer first
#pragma unroll
        for (int kk = 0; kk < 2; kk++) {
            uint32_t ahf[4][4], alf[4][4], bhf[2][4], blf[2][4];
#pragma unroll
            for (int mf = 0; mf < 4; mf++) {
                LDMX4(ahf[mf], sb + a_off[mf][kk]);
                LDMX4(alf[mf], sb + 8192 + a_off[mf][kk]);
            }
#pragma unroll
            for (int nf = 0; nf < 2; nf++) {
                LDMX4(bhf[nf], sb + 16384 + b_off[nf][kk]);
                LDMX4(blf[nf], sb + 24576 + b_off[nf][kk]);
            }
#pragma unroll
            for (int mf = 0; mf < 4; mf++)
#pragma unroll
                for (int j = 0; j < 4; j++) {
                    uint32_t b0h = bhf[j >> 1][(j & 1) * 2], b1h = bhf[j >> 1][(j & 1) * 2 + 1];
                    uint32_t b0l = blf[j >> 1][(j & 1) * 2], b1l = blf[j >> 1][(j & 1) * 2 + 1];
                    MMA(acc[mf][j], ahf[mf], b0h, b1h);
                    MMA(acc[mf][j], alf[mf], b0h, b1h);
                    MMA(acc[mf][j], ahf[mf], b0l, b1l);
                }
        }
        if (ch + 2 < NCH) ldg_chunk(ch + 2);
        __syncthreads();
    }

    // -------- epilogue --------
    int erow = lane >> 2;
    int ecol = (lane & 3) * 2;
#pragma unroll
    for (int mf = 0; mf < 4; mf++) {
        int mloc0 = m0 + warp_m * 64 + mf * 16 + erow;
        int mloc1 = mloc0 + 8;
#pragma unroll
        for (int j = 0; j < 4; j++) {
            int nglob = n0 + warp_n * 32 + j * 8 + ecol;
            if (mloc0 < cnt)
                *(float2*)(C + (size_t)(seg0 + mloc0) * ldc + nglob) = make_float2(acc[mf][j][0], acc[mf][j][1]);
            if (mloc1 < cnt)
                *(float2*)(C + (size_t)(seg0 + mloc1) * ldc + nglob) = make_float2(acc[mf][j][2], acc[mf][j][3]);
        }
    }
}

// ---------------- SwiGLU elementwise: fp32 gu -> pre-split bf16 h ----------------
__global__ __launch_bounds__(256) void swiglu_kernel(int npairs)
{
    int idx = blockIdx.x * blockDim.x + threadIdx.x;
    if (idx >= npairs * (IDIM / 4)) return;
    int p = idx / (IDIM / 4);
    int c = idx % (IDIM / 4);
    float4 g4 = ((const float4*)g_gu)[(size_t)p * (TWO_I / 4) + c];
    float4 u4 = ((const float4*)g_gu)[(size_t)p * (TWO_I / 4) + (IDIM / 4) + c];
    float4 h;
    h.x = u4.x * g4.x / (1.f + expf(-g4.x));
    h.y = u4.y * g4.y / (1.f + expf(-g4.y));
    h.z = u4.z * g4.z / (1.f + expf(-g4.z));
    h.w = u4.w * g4.w / (1.f + expf(-g4.w));
    uint32_t h01, h23, l01, l23;
    split4(h, h01, h23, l01, l23);
    ((uint2*)g_h_hi)[idx] = make_uint2(h01, h23);
    ((uint2*)g_h_lo)[idx] = make_uint2(l01, l23);
}

// ---------------- combine: out[t] = w0*y[p0] + w1*y[p1] ----------------
__global__ __launch_bounds__(256) void combine_kernel(float* __restrict__ out, int T)
{
    int idx = blockIdx.x * blockDim.x + threadIdx.x;
    if (idx >= T * (HDIM / 4)) return;
    int t = idx >> 9;
    int c = idx & 511;
    int p0 = g_tok_pair[2 * t], p1 = g_tok_pair[2 * t + 1];
    float w0 = g_tok_w[2 * t], w1 = g_tok_w[2 * t + 1];
    float4 a = ((const float4*)g_y)[(size_t)p0 * 512 + c];
    float4 b = ((const float4*)g_y)[(size_t)p1 * 512 + c];
    float4 o;
    o.x = w0 * a.x + w1 * b.x;
    o.y = w0 * a.y + w1 * b.y;
    o.z = w0 * a.z + w1 * b.z;
    o.w = w0 * a.w + w1 * b.w;
    ((float4*)out)[idx] = o;
}

// ---------------- launch ----------------
extern "C" void kernel_launch(void* const* d_in, const int* in_sizes, int n_in,
                              void* d_out, int out_size)
{
    const float* x   = (const float*)d_in[0];
    const float* gw  = (const float*)d_in[1];
    const float* gup = (const float*)d_in[2];
    const float* dw  = (const float*)d_in[3];
    float* out = (float*)d_out;

    int T = in_sizes[0] / HDIM;
    size_t main_sz = (size_t)T * HDIM;

    float* logits;
    if ((size_t)out_size >= main_sz + (size_t)T * NEXP) logits = out + main_sz;
    else cudaGetSymbolAddress((void**)&logits, g_logits_fallback);

    cudaFuncSetAttribute((const void*)gemm2<HDIM, 0>,
                         cudaFuncAttributeMaxDynamicSharedMemorySize, GSMEM);
    cudaFuncSetAttribute((const void*)gemm2<IDIM, 1>,
                         cudaFuncAttributeMaxDynamicSharedMemorySize, GSMEM);

    init_kernel<<<1, 32>>>();
    router_kernel<<<T, 128>>>(x, gw, logits, T);
    offsets_kernel<<<1, 32>>>();
    dispatch_kernel<<<(T + 127) / 128, 128>>>(T);

    int mtiles = (T + 127) / 128;

    float* d_gu; cudaGetSymbolAddress((void**)&d_gu, g_gu);
    float* d_y;  cudaGetSymbolAddress((void**)&d_y,  g_y);

    dim3 gu_grid(mtiles, TWO_I / 128, NEXP);
    gemm2<HDIM, 0><<<gu_grid, 256, GSMEM>>>(x, gup, d_gu, TWO_I, (size_t)TWO_I * HDIM);

    int npairs = 2 * T;
    swiglu_kernel<<<(npairs * (IDIM / 4) + 255) / 256, 256>>>(npairs);

    dim3 dn_grid(mtiles, HDIM / 128, NEXP);
    gemm2<IDIM, 1><<<dn_grid, 256, GSMEM>>>(nullptr, dw, d_y, HDIM, (size_t)HDIM * IDIM);

    combine_kernel<<<(T * (HDIM / 4) + 255) / 256, 256>>>(out, T);
}